// round 2
// baseline (speedup 1.0000x reference)
#include <cuda_runtime.h>
#include <cstdint>
#include <cstddef>

#define D_   2048
#define NC_  2
#define DS_  16
#define BL_  1024           // B*L = 2*512
#define N1_  4096           // NC*D

// ---------------- scratch (static device globals; no allocation) ----------
__device__ float g_xi[(size_t)BL_ * N1_];   // 16 MB
__device__ float g_y [(size_t)BL_ * N1_];   // 16 MB
__device__ float g_o [(size_t)BL_ * D_];    // 8 MB
__device__ float g_gate[N1_];

// ---------------- helpers --------------------------------------------------
__device__ __forceinline__ unsigned f2tf(float f) {
    unsigned u;
    asm("cvt.rna.tf32.f32 %0, %1;" : "=r"(u) : "f"(f));
    return u;
}

// ---------------- gate: g[n] = sum_ds(Cr*Br - Ci*Bi) -----------------------
__global__ void compute_gate(const float* __restrict__ Br, const float* __restrict__ Bi,
                             const float* __restrict__ Cr, const float* __restrict__ Ci) {
    int n = blockIdx.x * blockDim.x + threadIdx.x;
    if (n >= N1_) return;
    float s = 0.f;
    #pragma unroll
    for (int d = 0; d < DS_; d++)
        s = fmaf(Cr[n*DS_+d], Br[n*DS_+d], fmaf(-Ci[n*DS_+d], Bi[n*DS_+d], s));
    g_gate[n] = s;
}

// ---------------- TN GEMM: C[M,N] = A[M,K] * B[N,K]^T  (tf32 mma) ----------
// M,N multiples of 128; K multiple of 16. 256 threads, 128x128 tile, BK=16.
__global__ __launch_bounds__(256) void gemm_tn(
    const float* __restrict__ A, const float* __restrict__ B, float* __restrict__ C,
    int N, int K)
{
    const int PAD = 20;                       // bank-conflict-free fragment reads
    __shared__ float As[2][128 * PAD];
    __shared__ float Bs[2][128 * PAD];

    const int tid  = threadIdx.x;
    const int lane = tid & 31;
    const int wid  = tid >> 5;
    const int wm   = (wid & 3) * 32;          // warp m-offset (4 warps in m)
    const int wn   = (wid >> 2) * 64;         // warp n-offset (2 warps in n)
    const int gid  = lane >> 2;               // groupID
    const int q    = lane & 3;                // threadID_in_group
    const int row0 = blockIdx.y * 128;
    const int col0 = blockIdx.x * 128;

    const int lr = tid >> 2;                  // loader row (task 0)
    const int lc = (tid & 3) * 4;             // loader col (float4)

    float cr[2][8][4];
    #pragma unroll
    for (int i = 0; i < 2; i++)
        #pragma unroll
        for (int j = 0; j < 8; j++)
            #pragma unroll
            for (int t = 0; t < 4; t++) cr[i][j][t] = 0.f;

    float4 ra[2], rb[2];

    auto gload = [&](int k0) {
        #pragma unroll
        for (int i = 0; i < 2; i++) {
            int r = lr + i * 64;
            ra[i] = *reinterpret_cast<const float4*>(A + (size_t)(row0 + r) * K + k0 + lc);
            rb[i] = *reinterpret_cast<const float4*>(B + (size_t)(col0 + r) * K + k0 + lc);
        }
    };
    auto stage = [&](int buf) {
        #pragma unroll
        for (int i = 0; i < 2; i++) {
            int r = lr + i * 64;
            float* pa = &As[buf][r * PAD + lc];
            pa[0] = __uint_as_float(f2tf(ra[i].x));
            pa[1] = __uint_as_float(f2tf(ra[i].y));
            pa[2] = __uint_as_float(f2tf(ra[i].z));
            pa[3] = __uint_as_float(f2tf(ra[i].w));
            float* pb = &Bs[buf][r * PAD + lc];
            pb[0] = __uint_as_float(f2tf(rb[i].x));
            pb[1] = __uint_as_float(f2tf(rb[i].y));
            pb[2] = __uint_as_float(f2tf(rb[i].z));
            pb[3] = __uint_as_float(f2tf(rb[i].w));
        }
    };
    auto compute = [&](int buf) {
        #pragma unroll
        for (int ks = 0; ks < 2; ks++) {
            const int k8 = ks * 8;
            unsigned a[2][4], b[8][2];
            #pragma unroll
            for (int i = 0; i < 2; i++) {
                int r = wm + i * 16 + gid;
                a[i][0] = __float_as_uint(As[buf][ r      * PAD + k8 + q    ]);
                a[i][1] = __float_as_uint(As[buf][(r + 8) * PAD + k8 + q    ]);
                a[i][2] = __float_as_uint(As[buf][ r      * PAD + k8 + q + 4]);
                a[i][3] = __float_as_uint(As[buf][(r + 8) * PAD + k8 + q + 4]);
            }
            #pragma unroll
            for (int j = 0; j < 8; j++) {
                int n = wn + j * 8 + gid;
                b[j][0] = __float_as_uint(Bs[buf][n * PAD + k8 + q    ]);
                b[j][1] = __float_as_uint(Bs[buf][n * PAD + k8 + q + 4]);
            }
            #pragma unroll
            for (int i = 0; i < 2; i++)
                #pragma unroll
                for (int j = 0; j < 8; j++) {
                    asm volatile(
                        "mma.sync.aligned.m16n8k8.row.col.f32.tf32.tf32.f32 "
                        "{%0,%1,%2,%3}, {%4,%5,%6,%7}, {%8,%9}, {%0,%1,%2,%3};\n"
                        : "+f"(cr[i][j][0]), "+f"(cr[i][j][1]),
                          "+f"(cr[i][j][2]), "+f"(cr[i][j][3])
                        : "r"(a[i][0]), "r"(a[i][1]), "r"(a[i][2]), "r"(a[i][3]),
                          "r"(b[j][0]), "r"(b[j][1]));
                }
        }
    };

    const int nt = K / 16;
    gload(0);
    stage(0);
    __syncthreads();
    for (int kt = 0; kt < nt; kt++) {
        int buf = kt & 1;
        if (kt + 1 < nt) gload((kt + 1) * 16);
        compute(buf);
        if (kt + 1 < nt) {
            stage(buf ^ 1);
            __syncthreads();
        }
    }

    // epilogue
    #pragma unroll
    for (int i = 0; i < 2; i++)
        #pragma unroll
        for (int j = 0; j < 8; j++) {
            int r  = row0 + wm + i * 16 + gid;
            int cn = col0 + wn + j * 8 + q * 2;
            *reinterpret_cast<float2*>(C + (size_t)r * N + cn) =
                make_float2(cr[i][j][0], cr[i][j][1]);
            *reinterpret_cast<float2*>(C + (size_t)(r + 8) * N + cn) =
                make_float2(cr[i][j][2], cr[i][j][3]);
        }
}

// ---------------- elementwise: y = xi*g ; nr = Br*xi ; ni = Bi*xi ----------
__global__ void ew_kernel(const float* __restrict__ Br, const float* __restrict__ Bi,
                          float* __restrict__ nr, float* __restrict__ ni,
                          int write_state)
{
    int e = blockIdx.x * blockDim.x + threadIdx.x;   // 0 .. BL_*N1_-1
    int n = e & (N1_ - 1);
    float v = g_xi[e];
    g_y[e] = v * g_gate[n];
    if (write_state) {
        const float4* br = reinterpret_cast<const float4*>(Br) + (size_t)n * 4;
        const float4* bi = reinterpret_cast<const float4*>(Bi) + (size_t)n * 4;
        float4* pr = reinterpret_cast<float4*>(nr) + (size_t)e * 4;
        float4* pi = reinterpret_cast<float4*>(ni) + (size_t)e * 4;
        #pragma unroll
        for (int j = 0; j < 4; j++) {
            float4 b = __ldg(&br[j]);
            pr[j] = make_float4(b.x * v, b.y * v, b.z * v, b.w * v);
        }
        #pragma unroll
        for (int j = 0; j < 4; j++) {
            float4 b = __ldg(&bi[j]);
            pi[j] = make_float4(b.x * v, b.y * v, b.z * v, b.w * v);
        }
    }
}

// ---------------- rmsnorm + residual ---------------------------------------
__global__ __launch_bounds__(256) void rms_kernel(const float* __restrict__ x,
                                                  const float* __restrict__ w,
                                                  float* __restrict__ out)
{
    const int row = blockIdx.x;
    const float* o = g_o + (size_t)row * D_;
    float s = 0.f;
    for (int d = threadIdx.x; d < D_; d += 256) {
        float v = o[d];
        s = fmaf(v, v, s);
    }
    __shared__ float red[8];
    #pragma unroll
    for (int off = 16; off; off >>= 1) s += __shfl_xor_sync(0xFFFFFFFFu, s, off);
    if ((threadIdx.x & 31) == 0) red[threadIdx.x >> 5] = s;
    __syncthreads();
    if (threadIdx.x < 8) {
        float t = red[threadIdx.x];
        #pragma unroll
        for (int off = 4; off; off >>= 1) t += __shfl_xor_sync(0xFFu, t, off);
        if (threadIdx.x == 0) red[0] = t;
    }
    __syncthreads();
    const float scale = rsqrtf(red[0] * (1.0f / D_) + 1.1920928955078125e-7f);
    for (int d = threadIdx.x; d < D_; d += 256) {
        out[(size_t)row * D_ + d] =
            x[(size_t)row * D_ + d] + o[d] * scale * w[d];
    }
}

// ---------------- launch ----------------------------------------------------
extern "C" void kernel_launch(void* const* d_in, const int* in_sizes, int n_in,
                              void* d_out, int out_size)
{
    const float* x     = (const float*)d_in[0];
    const float* W_in  = (const float*)d_in[1];
    const float* W_out = (const float*)d_in[2];
    // d_in[3] = A_theta: dead (initial state is zero)
    const float* Br    = (const float*)d_in[4];
    const float* Bi    = (const float*)d_in[5];
    const float* Cr    = (const float*)d_in[6];
    const float* Ci    = (const float*)d_in[7];
    const float* nw    = (const float*)d_in[8];

    float* out0 = (float*)d_out;
    const long long FULL =
        (long long)BL_ * D_ + 2LL * BL_ * N1_ * DS_;   // 136,314,880
    const int write_state = ((long long)out_size >= FULL) ? 1 : 0;
    float* nr = out0 + (size_t)BL_ * D_;
    float* ni = nr + (size_t)BL_ * N1_ * DS_;

    void *xi_p = nullptr, *y_p = nullptr, *o_p = nullptr;
    cudaGetSymbolAddress(&xi_p, g_xi);
    cudaGetSymbolAddress(&y_p,  g_y);
    cudaGetSymbolAddress(&o_p,  g_o);

    compute_gate<<<N1_ / 256, 256>>>(Br, Bi, Cr, Ci);

    // xi = x @ W_in^T : M=1024, N=4096, K=2048
    gemm_tn<<<dim3(N1_ / 128, BL_ / 128), 256>>>(x, W_in, (float*)xi_p, N1_, D_);

    // y = xi * g ; nr/ni emission
    ew_kernel<<<(BL_ * N1_) / 256, 256>>>(Br, Bi, nr, ni, write_state);

    // out = y @ W_out^T : M=1024, N=2048, K=4096
    gemm_tn<<<dim3(D_ / 128, BL_ / 128), 256>>>((const float*)y_p, W_out, (float*)o_p,
                                                D_, N1_);

    // out0 = x + rmsnorm(out) * w
    rms_kernel<<<BL_, 256>>>(x, nw, out0);
}

// round 3
// speedup vs baseline: 1.4948x; 1.4948x over previous
#include <cuda_runtime.h>
#include <cstdint>
#include <cstddef>

#define D_   2048
#define NC_  2
#define DS_  16
#define BL_  1024           // B*L = 2*512
#define N1_  4096           // NC*D

// ---------------- scratch (static device globals; no allocation) -----------
__device__ float g_Wr1[(size_t)N1_ * D_];   // rounded W_in   (32 MB)
__device__ float g_Wr2[(size_t)D_ * N1_];   // rounded W_out  (32 MB)
__device__ float g_xr [(size_t)BL_ * D_];   // rounded x      (4 MB)
__device__ float g_y  [(size_t)BL_ * N1_];  // y = rnd(xi*gate) (16 MB)
__device__ float g_o  [(size_t)BL_ * D_];   // out pre-norm   (8 MB)
__device__ float g_gate[N1_];

// ---------------- helpers ---------------------------------------------------
__device__ __forceinline__ float f2tf(float f) {
    unsigned u;
    asm("cvt.rna.tf32.f32 %0, %1;" : "=r"(u) : "f"(f));
    return __uint_as_float(u);
}

__device__ __forceinline__ void cpa16(float* s, const float* g) {
    unsigned sa = (unsigned)__cvta_generic_to_shared(s);
    asm volatile("cp.async.cg.shared.global [%0], [%1], 16;\n" :: "r"(sa), "l"(g));
}

// ---------------- pre-round to tf32 -----------------------------------------
__global__ void round_copy(const float4* __restrict__ s, float4* __restrict__ d, int n4) {
    int i = blockIdx.x * blockDim.x + threadIdx.x;
    if (i >= n4) return;
    float4 v = s[i];
    d[i] = make_float4(f2tf(v.x), f2tf(v.y), f2tf(v.z), f2tf(v.w));
}

// ---------------- gate: g[n] = sum_ds(Cr*Br - Ci*Bi) ------------------------
__global__ void compute_gate(const float* __restrict__ Br, const float* __restrict__ Bi,
                             const float* __restrict__ Cr, const float* __restrict__ Ci) {
    int n = blockIdx.x * blockDim.x + threadIdx.x;
    if (n >= N1_) return;
    float s = 0.f;
    #pragma unroll
    for (int d = 0; d < DS_; d++)
        s = fmaf(Cr[n*DS_+d], Br[n*DS_+d], fmaf(-Ci[n*DS_+d], Bi[n*DS_+d], s));
    g_gate[n] = s;
}

// ---------------- state emission helper -------------------------------------
__device__ __forceinline__ void emit_state(float* __restrict__ nr, float* __restrict__ ni,
                                           const float4* __restrict__ brp,
                                           const float4* __restrict__ bip,
                                           int row, int col, float v) {
    size_t off = ((size_t)row * N1_ + col) * 4;          // float4 units
    float4* pr = reinterpret_cast<float4*>(nr) + off;
    float4* pi = reinterpret_cast<float4*>(ni) + off;
    #pragma unroll
    for (int jj = 0; jj < 4; jj++) {
        float4 b = __ldg(&brp[(size_t)col * 4 + jj]);
        pr[jj] = make_float4(b.x * v, b.y * v, b.z * v, b.w * v);
    }
    #pragma unroll
    for (int jj = 0; jj < 4; jj++) {
        float4 b = __ldg(&bip[(size_t)col * 4 + jj]);
        pi[jj] = make_float4(b.x * v, b.y * v, b.z * v, b.w * v);
    }
}

// ---------------- TN GEMM: C[M,N] = A[M,K] * B[N,K]^T (tf32 mma, cp.async) --
// BM x 128 CTA tile, BK=16, 4-stage cp.async pipeline, 256 threads.
// FUSED: epilogue writes y = rnd(acc*gate) into C and emits nr/ni.
template<int BM, bool FUSED>
__global__ __launch_bounds__(256, 2) void gemm_tn(
    const float* __restrict__ A, const float* __restrict__ B, float* __restrict__ C,
    int N, int K,
    const float* __restrict__ Brs, const float* __restrict__ Bis,
    float* __restrict__ nr, float* __restrict__ ni, int write_state)
{
    constexpr int S   = 4;                    // pipeline stages
    constexpr int WR  = (BM == 128) ? 4 : 2;  // warps along m
    constexpr int WNS = (BM == 128) ? 64 : 32;// warp n-extent
    constexpr int JN  = WNS / 8;
    constexpr int AST = BM  * 20;             // floats per A stage (PAD=20)
    constexpr int BST = 128 * 20;

    extern __shared__ float sm[];
    float* As = sm;
    float* Bs = sm + S * AST;

    const int tid  = threadIdx.x;
    const int lane = tid & 31;
    const int wid  = tid >> 5;
    const int wm   = (wid % WR) * 32;
    const int wn   = (wid / WR) * WNS;
    const int gid  = lane >> 2;
    const int q    = lane & 3;
    const int row0 = blockIdx.y * BM;
    const int col0 = blockIdx.x * 128;

    const int lr = tid >> 2;
    const int lc = (tid & 3) * 4;

    float cr[2][JN][4];
    #pragma unroll
    for (int i = 0; i < 2; i++)
        #pragma unroll
        for (int j = 0; j < JN; j++)
            #pragma unroll
            for (int t = 0; t < 4; t++) cr[i][j][t] = 0.f;

    auto issue = [&](int st, int k0) {
        #pragma unroll
        for (int i = 0; i < BM / 64; i++) {
            int r = lr + i * 64;
            cpa16(&As[st * AST + r * 20 + lc], A + (size_t)(row0 + r) * K + k0 + lc);
        }
        #pragma unroll
        for (int i = 0; i < 2; i++) {
            int r = lr + i * 64;
            cpa16(&Bs[st * BST + r * 20 + lc], B + (size_t)(col0 + r) * K + k0 + lc);
        }
        asm volatile("cp.async.commit_group;\n");
    };

    auto compute = [&](int st) {
        const float* as = As + st * AST;
        const float* bs = Bs + st * BST;
        #pragma unroll
        for (int ks = 0; ks < 2; ks++) {
            const int k8 = ks * 8;
            unsigned a[2][4], b[JN][2];
            #pragma unroll
            for (int i = 0; i < 2; i++) {
                int r = wm + i * 16 + gid;
                a[i][0] = __float_as_uint(as[ r      * 20 + k8 + q    ]);
                a[i][1] = __float_as_uint(as[(r + 8) * 20 + k8 + q    ]);
                a[i][2] = __float_as_uint(as[ r      * 20 + k8 + q + 4]);
                a[i][3] = __float_as_uint(as[(r + 8) * 20 + k8 + q + 4]);
            }
            #pragma unroll
            for (int j = 0; j < JN; j++) {
                int n = wn + j * 8 + gid;
                b[j][0] = __float_as_uint(bs[n * 20 + k8 + q    ]);
                b[j][1] = __float_as_uint(bs[n * 20 + k8 + q + 4]);
            }
            #pragma unroll
            for (int i = 0; i < 2; i++)
                #pragma unroll
                for (int j = 0; j < JN; j++) {
                    asm volatile(
                        "mma.sync.aligned.m16n8k8.row.col.f32.tf32.tf32.f32 "
                        "{%0,%1,%2,%3}, {%4,%5,%6,%7}, {%8,%9}, {%0,%1,%2,%3};\n"
                        : "+f"(cr[i][j][0]), "+f"(cr[i][j][1]),
                          "+f"(cr[i][j][2]), "+f"(cr[i][j][3])
                        : "r"(a[i][0]), "r"(a[i][1]), "r"(a[i][2]), "r"(a[i][3]),
                          "r"(b[j][0]), "r"(b[j][1]));
                }
        }
    };

    const int nt = K / 16;
    #pragma unroll
    for (int s = 0; s < S - 1; s++) issue(s, s * 16);
    asm volatile("cp.async.wait_group 2;\n");
    __syncthreads();

    for (int kt = 0; kt < nt; kt++) {
        int nk = kt + S - 1;
        if (nk < nt) issue(nk % S, nk * 16);
        else asm volatile("cp.async.commit_group;\n");
        compute(kt % S);
        asm volatile("cp.async.wait_group 2;\n");
        __syncthreads();
    }

    // ---------------- epilogue ----------------
    if (!FUSED) {
        #pragma unroll
        for (int i = 0; i < 2; i++)
            #pragma unroll
            for (int j = 0; j < JN; j++) {
                int r  = row0 + wm + i * 16 + gid;
                int cn = col0 + wn + j * 8 + q * 2;
                *reinterpret_cast<float2*>(C + (size_t)r * N + cn) =
                    make_float2(cr[i][j][0], cr[i][j][1]);
                *reinterpret_cast<float2*>(C + (size_t)(r + 8) * N + cn) =
                    make_float2(cr[i][j][2], cr[i][j][3]);
            }
    } else {
        const float4* brp = reinterpret_cast<const float4*>(Brs);
        const float4* bip = reinterpret_cast<const float4*>(Bis);
        #pragma unroll
        for (int i = 0; i < 2; i++)
            #pragma unroll
            for (int j = 0; j < JN; j++) {
                int r  = row0 + wm + i * 16 + gid;
                int cn = col0 + wn + j * 8 + q * 2;
                float g0 = g_gate[cn], g1 = g_gate[cn + 1];
                *reinterpret_cast<float2*>(C + (size_t)r * N + cn) =
                    make_float2(f2tf(cr[i][j][0] * g0), f2tf(cr[i][j][1] * g1));
                *reinterpret_cast<float2*>(C + (size_t)(r + 8) * N + cn) =
                    make_float2(f2tf(cr[i][j][2] * g0), f2tf(cr[i][j][3] * g1));
                if (write_state) {
                    emit_state(nr, ni, brp, bip, r,     cn,     cr[i][j][0]);
                    emit_state(nr, ni, brp, bip, r,     cn + 1, cr[i][j][1]);
                    emit_state(nr, ni, brp, bip, r + 8, cn,     cr[i][j][2]);
                    emit_state(nr, ni, brp, bip, r + 8, cn + 1, cr[i][j][3]);
                }
            }
    }
}

// ---------------- rmsnorm + residual ----------------------------------------
__global__ __launch_bounds__(256) void rms_kernel(const float* __restrict__ x,
                                                  const float* __restrict__ w,
                                                  float* __restrict__ out)
{
    const int row = blockIdx.x;
    const float* o = g_o + (size_t)row * D_;
    float s = 0.f;
    for (int d = threadIdx.x; d < D_; d += 256) {
        float v = o[d];
        s = fmaf(v, v, s);
    }
    __shared__ float red[8];
    #pragma unroll
    for (int off = 16; off; off >>= 1) s += __shfl_xor_sync(0xFFFFFFFFu, s, off);
    if ((threadIdx.x & 31) == 0) red[threadIdx.x >> 5] = s;
    __syncthreads();
    if (threadIdx.x < 8) {
        float t = red[threadIdx.x];
        #pragma unroll
        for (int off = 4; off; off >>= 1) t += __shfl_xor_sync(0xFFu, t, off);
        if (threadIdx.x == 0) red[0] = t;
    }
    __syncthreads();
    const float scale = rsqrtf(red[0] * (1.0f / D_) + 1.1920928955078125e-7f);
    for (int d = threadIdx.x; d < D_; d += 256) {
        out[(size_t)row * D_ + d] =
            x[(size_t)row * D_ + d] + o[d] * scale * w[d];
    }
}

// ---------------- launch -----------------------------------------------------
extern "C" void kernel_launch(void* const* d_in, const int* in_sizes, int n_in,
                              void* d_out, int out_size)
{
    const float* x     = (const float*)d_in[0];
    const float* W_in  = (const float*)d_in[1];
    const float* W_out = (const float*)d_in[2];
    // d_in[3] = A_theta: dead (initial state is zero)
    const float* Br    = (const float*)d_in[4];
    const float* Bi    = (const float*)d_in[5];
    const float* Cr    = (const float*)d_in[6];
    const float* Ci    = (const float*)d_in[7];
    const float* nw    = (const float*)d_in[8];

    float* out0 = (float*)d_out;
    const long long FULL =
        (long long)BL_ * D_ + 2LL * BL_ * N1_ * DS_;   // 136,314,880
    const int write_state = ((long long)out_size >= FULL) ? 1 : 0;
    float* nr = out0 + (size_t)BL_ * D_;
    float* ni = nr + (size_t)BL_ * N1_ * DS_;

    void *w1_p = nullptr, *w2_p = nullptr, *xr_p = nullptr, *y_p = nullptr, *o_p = nullptr;
    cudaGetSymbolAddress(&w1_p, g_Wr1);
    cudaGetSymbolAddress(&w2_p, g_Wr2);
    cudaGetSymbolAddress(&xr_p, g_xr);
    cudaGetSymbolAddress(&y_p,  g_y);
    cudaGetSymbolAddress(&o_p,  g_o);

    const int SM1 = 4 * (128 * 20 + 128 * 20) * 4;   // 81920 B
    const int SM2 = 4 * ( 64 * 20 + 128 * 20) * 4;   // 61440 B
    cudaFuncSetAttribute(gemm_tn<128, true >, cudaFuncAttributeMaxDynamicSharedMemorySize, SM1);
    cudaFuncSetAttribute(gemm_tn< 64, false>, cudaFuncAttributeMaxDynamicSharedMemorySize, SM2);

    // pre-round inputs to tf32 (hot loops stay cvt-free)
    round_copy<<<(N1_ * D_ / 4 + 255) / 256, 256>>>((const float4*)W_in,  (float4*)w1_p, N1_ * D_ / 4);
    round_copy<<<(D_ * N1_ / 4 + 255) / 256, 256>>>((const float4*)W_out, (float4*)w2_p, D_ * N1_ / 4);
    round_copy<<<(BL_ * D_ / 4 + 255) / 256, 256>>>((const float4*)x,     (float4*)xr_p, BL_ * D_ / 4);

    compute_gate<<<N1_ / 256, 256>>>(Br, Bi, Cr, Ci);

    // GEMM1 (fused): xi = x @ W_in^T, emit y / nr / ni.  M=1024,N=4096,K=2048
    gemm_tn<128, true><<<dim3(N1_ / 128, BL_ / 128), 256, SM1>>>(
        (const float*)xr_p, (const float*)w1_p, (float*)y_p, N1_, D_,
        Br, Bi, nr, ni, write_state);

    // GEMM2: out = y @ W_out^T.  M=1024,N=2048,K=4096  (64-row tiles -> 256 CTAs)
    gemm_tn<64, false><<<dim3(D_ / 128, BL_ / 64), 256, SM2>>>(
        (const float*)y_p, (const float*)w2_p, (float*)o_p, D_, N1_,
        nullptr, nullptr, nullptr, nullptr, 0);

    // out0 = x + rmsnorm(out) * norm_w
    rms_kernel<<<BL_, 256>>>(x, nw, out0);
}

// round 5
// speedup vs baseline: 2.0201x; 1.3514x over previous
#include <cuda_runtime.h>
#include <cuda_fp16.h>
#include <cstdint>
#include <cstddef>

#define D_   2048
#define NC_  2
#define DS_  16
#define BL_  1024           // B*L = 2*512
#define N1_  4096           // NC*D

// ---------------- scratch (static device globals; no allocation) -----------
__device__ __half g_Wh1[(size_t)N1_ * D_];   // fp16 W_in   (16 MB)
__device__ __half g_Wh2[(size_t)D_ * N1_];   // fp16 W_out  (16 MB)
__device__ __half g_xh [(size_t)BL_ * D_];   // fp16 x      (2 MB)
__device__ __half g_yh [(size_t)BL_ * N1_];  // fp16 y = xi*gate (8 MB)
__device__ float  g_o  [(size_t)BL_ * D_];   // out pre-norm (8 MB)
__device__ float  g_gate[N1_];

// ---------------- helpers ---------------------------------------------------
__device__ __forceinline__ void cpa16(const void* s, const void* g) {
    unsigned sa = (unsigned)__cvta_generic_to_shared(s);
    asm volatile("cp.async.cg.shared.global [%0], [%1], 16;\n" :: "r"(sa), "l"(g));
}

// ---------------- fp32 -> fp16 convert --------------------------------------
__global__ void to_half(const float4* __restrict__ s, __half2* __restrict__ d, int n4) {
    int i = blockIdx.x * blockDim.x + threadIdx.x;
    if (i >= n4) return;
    float4 v = s[i];
    d[2 * i]     = __floats2half2_rn(v.x, v.y);
    d[2 * i + 1] = __floats2half2_rn(v.z, v.w);
}

// ---------------- gate: g[n] = sum_ds(Cr*Br - Ci*Bi) ------------------------
__global__ void compute_gate(const float4* __restrict__ Br, const float4* __restrict__ Bi,
                             const float4* __restrict__ Cr, const float4* __restrict__ Ci) {
    int n = blockIdx.x * blockDim.x + threadIdx.x;
    if (n >= N1_) return;
    float s = 0.f;
    #pragma unroll
    for (int j = 0; j < 4; j++) {
        float4 cr = Cr[n * 4 + j], br = Br[n * 4 + j];
        float4 ci = Ci[n * 4 + j], bi = Bi[n * 4 + j];
        s = fmaf(cr.x, br.x, s); s = fmaf(-ci.x, bi.x, s);
        s = fmaf(cr.y, br.y, s); s = fmaf(-ci.y, bi.y, s);
        s = fmaf(cr.z, br.z, s); s = fmaf(-ci.z, bi.z, s);
        s = fmaf(cr.w, br.w, s); s = fmaf(-ci.w, bi.w, s);
    }
    g_gate[n] = s;
}

// ---------------- state emission helper -------------------------------------
__device__ __forceinline__ void emit_state(float* __restrict__ nr, float* __restrict__ ni,
                                           const float4* __restrict__ brp,
                                           const float4* __restrict__ bip,
                                           int row, int col, float v) {
    size_t off = ((size_t)row * N1_ + col) * 4;          // float4 units
    float4* pr = reinterpret_cast<float4*>(nr) + off;
    float4* pi = reinterpret_cast<float4*>(ni) + off;
    #pragma unroll
    for (int jj = 0; jj < 4; jj++) {
        float4 b = __ldg(&brp[(size_t)col * 4 + jj]);
        pr[jj] = make_float4(b.x * v, b.y * v, b.z * v, b.w * v);
    }
    #pragma unroll
    for (int jj = 0; jj < 4; jj++) {
        float4 b = __ldg(&bip[(size_t)col * 4 + jj]);
        pi[jj] = make_float4(b.x * v, b.y * v, b.z * v, b.w * v);
    }
}

// ---------------- TN GEMM: C[M,N] = A[M,K] * B[N,K]^T (fp16 mma, cp.async) --
// BM x 128 CTA tile, BK=32 halves, 4-stage cp.async pipeline, 256 threads.
// FUSED: epilogue writes y_half = acc*gate and emits nr/ni.
template<int BM, bool FUSED>
__global__ __launch_bounds__(256, 2) void gemm_tn(
    const __half* __restrict__ A, const __half* __restrict__ B,
    float* __restrict__ Cf, __half* __restrict__ Ch, int ldc, int K,
    const float* __restrict__ Brs, const float* __restrict__ Bis,
    float* __restrict__ nr, float* __restrict__ ni, int write_state)
{
    constexpr int S   = 4;                    // pipeline stages
    constexpr int RS  = 40;                   // halves per smem row (32 + 8 pad)
    constexpr int WR  = (BM == 128) ? 4 : 2;  // warps along m
    constexpr int WNS = (BM == 128) ? 64 : 32;// warp n-extent
    constexpr int JN  = WNS / 8;
    constexpr int AST = BM  * RS;             // halves per A stage
    constexpr int BST = 128 * RS;

    extern __shared__ __half sm[];
    __half* As = sm;
    __half* Bs = sm + S * AST;

    const int tid  = threadIdx.x;
    const int lane = tid & 31;
    const int wid  = tid >> 5;
    const int wm   = (wid % WR) * 32;
    const int wn   = (wid / WR) * WNS;
    const int gid  = lane >> 2;
    const int q    = lane & 3;
    const int row0 = blockIdx.y * BM;
    const int col0 = blockIdx.x * 128;

    const int lr = tid >> 2;                  // loader row
    const int ls = (tid & 3) * 8;             // loader half-offset (16B = 8 halves)

    float cr[2][JN][4];
    #pragma unroll
    for (int i = 0; i < 2; i++)
        #pragma unroll
        for (int j = 0; j < JN; j++)
            #pragma unroll
            for (int t = 0; t < 4; t++) cr[i][j][t] = 0.f;

    auto issue = [&](int st, int k0) {
        #pragma unroll
        for (int i = 0; i < BM / 64; i++) {
            int r = lr + i * 64;
            cpa16(&As[st * AST + r * RS + ls], A + (size_t)(row0 + r) * K + k0 + ls);
        }
        #pragma unroll
        for (int i = 0; i < 2; i++) {
            int r = lr + i * 64;
            cpa16(&Bs[st * BST + r * RS + ls], B + (size_t)(col0 + r) * K + k0 + ls);
        }
        asm volatile("cp.async.commit_group;\n");
    };

    auto compute = [&](int st) {
        const __half* as = As + st * AST;
        const __half* bs = Bs + st * BST;
        #pragma unroll
        for (int ks = 0; ks < 2; ks++) {
            const int kb = ks * 16;
            unsigned a[2][4], b[JN][2];
            #pragma unroll
            for (int i = 0; i < 2; i++) {
                int r = wm + i * 16 + gid;
                a[i][0] = *reinterpret_cast<const unsigned*>(&as[ r      * RS + kb + 2 * q    ]);
                a[i][1] = *reinterpret_cast<const unsigned*>(&as[(r + 8) * RS + kb + 2 * q    ]);
                a[i][2] = *reinterpret_cast<const unsigned*>(&as[ r      * RS + kb + 2 * q + 8]);
                a[i][3] = *reinterpret_cast<const unsigned*>(&as[(r + 8) * RS + kb + 2 * q + 8]);
            }
            #pragma unroll
            for (int j = 0; j < JN; j++) {
                int n = wn + j * 8 + gid;
                b[j][0] = *reinterpret_cast<const unsigned*>(&bs[n * RS + kb + 2 * q    ]);
                b[j][1] = *reinterpret_cast<const unsigned*>(&bs[n * RS + kb + 2 * q + 8]);
            }
            #pragma unroll
            for (int i = 0; i < 2; i++)
                #pragma unroll
                for (int j = 0; j < JN; j++) {
                    asm volatile(
                        "mma.sync.aligned.m16n8k16.row.col.f32.f16.f16.f32 "
                        "{%0,%1,%2,%3}, {%4,%5,%6,%7}, {%8,%9}, {%0,%1,%2,%3};\n"
                        : "+f"(cr[i][j][0]), "+f"(cr[i][j][1]),
                          "+f"(cr[i][j][2]), "+f"(cr[i][j][3])
                        : "r"(a[i][0]), "r"(a[i][1]), "r"(a[i][2]), "r"(a[i][3]),
                          "r"(b[j][0]), "r"(b[j][1]));
                }
        }
    };

    const int nt = K / 32;
    #pragma unroll
    for (int s = 0; s < S - 1; s++) issue(s, s * 32);
    asm volatile("cp.async.wait_group 2;\n");
    __syncthreads();

    for (int kt = 0; kt < nt; kt++) {
        int nk = kt + S - 1;
        if (nk < nt) issue(nk % S, nk * 32);
        else asm volatile("cp.async.commit_group;\n");
        compute(kt % S);
        asm volatile("cp.async.wait_group 2;\n");
        __syncthreads();
    }

    // ---------------- epilogue ----------------
    if (!FUSED) {
        #pragma unroll
        for (int i = 0; i < 2; i++)
            #pragma unroll
            for (int j = 0; j < JN; j++) {
                int r  = row0 + wm + i * 16 + gid;
                int cn = col0 + wn + j * 8 + q * 2;
                *reinterpret_cast<float2*>(Cf + (size_t)r * ldc + cn) =
                    make_float2(cr[i][j][0], cr[i][j][1]);
                *reinterpret_cast<float2*>(Cf + (size_t)(r + 8) * ldc + cn) =
                    make_float2(cr[i][j][2], cr[i][j][3]);
            }
    } else {
        const float4* brp = reinterpret_cast<const float4*>(Brs);
        const float4* bip = reinterpret_cast<const float4*>(Bis);
        #pragma unroll
        for (int i = 0; i < 2; i++)
            #pragma unroll
            for (int j = 0; j < JN; j++) {
                int r  = row0 + wm + i * 16 + gid;
                int cn = col0 + wn + j * 8 + q * 2;
                float g0 = g_gate[cn], g1 = g_gate[cn + 1];
                *reinterpret_cast<__half2*>(Ch + (size_t)r * ldc + cn) =
                    __floats2half2_rn(cr[i][j][0] * g0, cr[i][j][1] * g1);
                *reinterpret_cast<__half2*>(Ch + (size_t)(r + 8) * ldc + cn) =
                    __floats2half2_rn(cr[i][j][2] * g0, cr[i][j][3] * g1);
                if (write_state) {
                    emit_state(nr, ni, brp, bip, r,     cn,     cr[i][j][0]);
                    emit_state(nr, ni, brp, bip, r,     cn + 1, cr[i][j][1]);
                    emit_state(nr, ni, brp, bip, r + 8, cn,     cr[i][j][2]);
                    emit_state(nr, ni, brp, bip, r + 8, cn + 1, cr[i][j][3]);
                }
            }
    }
}

// ---------------- rmsnorm + residual ----------------------------------------
__global__ __launch_bounds__(256) void rms_kernel(const float* __restrict__ x,
                                                  const float* __restrict__ w,
                                                  float* __restrict__ out)
{
    const int row = blockIdx.x;
    const float* o = g_o + (size_t)row * D_;
    float s = 0.f;
    for (int d = threadIdx.x; d < D_; d += 256) {
        float v = o[d];
        s = fmaf(v, v, s);
    }
    __shared__ float red[8];
    #pragma unroll
    for (int off = 16; off; off >>= 1) s += __shfl_xor_sync(0xFFFFFFFFu, s, off);
    if ((threadIdx.x & 31) == 0) red[threadIdx.x >> 5] = s;
    __syncthreads();
    if (threadIdx.x < 8) {
        float t = red[threadIdx.x];
        #pragma unroll
        for (int off = 4; off; off >>= 1) t += __shfl_xor_sync(0xFFu, t, off);
        if (threadIdx.x == 0) red[0] = t;
    }
    __syncthreads();
    const float scale = rsqrtf(red[0] * (1.0f / D_) + 1.1920928955078125e-7f);
    for (int d = threadIdx.x; d < D_; d += 256) {
        out[(size_t)row * D_ + d] =
            x[(size_t)row * D_ + d] + o[d] * scale * w[d];
    }
}

// ---------------- launch -----------------------------------------------------
extern "C" void kernel_launch(void* const* d_in, const int* in_sizes, int n_in,
                              void* d_out, int out_size)
{
    const float* x     = (const float*)d_in[0];
    const float* W_in  = (const float*)d_in[1];
    const float* W_out = (const float*)d_in[2];
    // d_in[3] = A_theta: dead (initial state is zero)
    const float* Br    = (const float*)d_in[4];
    const float* Bi    = (const float*)d_in[5];
    const float* Cr    = (const float*)d_in[6];
    const float* Ci    = (const float*)d_in[7];
    const float* nw    = (const float*)d_in[8];

    float* out0 = (float*)d_out;
    const long long FULL =
        (long long)BL_ * D_ + 2LL * BL_ * N1_ * DS_;   // 136,314,880
    const int write_state = ((long long)out_size >= FULL) ? 1 : 0;
    float* nr = out0 + (size_t)BL_ * D_;
    float* ni = nr + (size_t)BL_ * N1_ * DS_;

    void *w1_p = nullptr, *w2_p = nullptr, *xh_p = nullptr, *yh_p = nullptr, *o_p = nullptr;
    cudaGetSymbolAddress(&w1_p, g_Wh1);
    cudaGetSymbolAddress(&w2_p, g_Wh2);
    cudaGetSymbolAddress(&xh_p, g_xh);
    cudaGetSymbolAddress(&yh_p, g_yh);
    cudaGetSymbolAddress(&o_p,  g_o);

    const int SM1 = 4 * (128 + 128) * 40 * 2;   // 81,920 B
    const int SM2 = 4 * ( 64 + 128) * 40 * 2;   // 61,440 B
    cudaFuncSetAttribute(gemm_tn<128, true >, cudaFuncAttributeMaxDynamicSharedMemorySize, SM1);
    cudaFuncSetAttribute(gemm_tn< 64, false>, cudaFuncAttributeMaxDynamicSharedMemorySize, SM2);

    // convert inputs to fp16
    to_half<<<(N1_ * D_ / 4 + 255) / 256, 256>>>((const float4*)W_in,  (__half2*)w1_p, N1_ * D_ / 4);
    to_half<<<(D_ * N1_ / 4 + 255) / 256, 256>>>((const float4*)W_out, (__half2*)w2_p, D_ * N1_ / 4);
    to_half<<<(BL_ * D_ / 4 + 255) / 256, 256>>>((const float4*)x,     (__half2*)xh_p, BL_ * D_ / 4);

    compute_gate<<<N1_ / 128, 128>>>((const float4*)Br, (const float4*)Bi,
                                     (const float4*)Cr, (const float4*)Ci);

    // GEMM1 (fused): xi = x @ W_in^T -> y(half) / nr / ni.  M=1024,N=4096,K=2048
    gemm_tn<128, true><<<dim3(N1_ / 128, BL_ / 128), 256, SM1>>>(
        (const __half*)xh_p, (const __half*)w1_p, nullptr, (__half*)yh_p, N1_, D_,
        Br, Bi, nr, ni, write_state);

    // GEMM2: out = y @ W_out^T.  M=1024,N=2048,K=4096  (64-row tiles -> 256 CTAs)
    gemm_tn<64, false><<<dim3(D_ / 128, BL_ / 64), 256, SM2>>>(
        (const __half*)yh_p, (const __half*)w2_p, (float*)o_p, nullptr, D_, N1_,
        nullptr, nullptr, nullptr, nullptr, 0);

    // out0 = x + rmsnorm(out) * norm_w
    rms_kernel<<<BL_, 256>>>(x, nw, out0);
}

// round 6
// speedup vs baseline: 2.0615x; 1.0205x over previous
#include <cuda_runtime.h>
#include <cuda_fp16.h>
#include <cstdint>
#include <cstddef>

#define D_   2048
#define NC_  2
#define DS_  16
#define BL_  1024           // B*L = 2*512
#define N1_  4096           // NC*D

// ---------------- scratch (static device globals; no allocation) -----------
__device__ __half g_Wh1[(size_t)N1_ * D_];   // fp16 W_in   (16 MB)
__device__ __half g_Wh2[(size_t)D_ * N1_];   // fp16 W_out  (16 MB)
__device__ __half g_xh [(size_t)BL_ * D_];   // fp16 x      (2 MB)
__device__ __half g_yh [(size_t)BL_ * N1_];  // fp16 y = xi*gate (8 MB)
__device__ float  g_o  [(size_t)BL_ * D_];   // out pre-norm (8 MB)
__device__ float  g_gate[N1_];

// ---------------- helpers ---------------------------------------------------
__device__ __forceinline__ void cpa16(const void* s, const void* g) {
    unsigned sa = (unsigned)__cvta_generic_to_shared(s);
    asm volatile("cp.async.cg.shared.global [%0], [%1], 16;\n" :: "r"(sa), "l"(g));
}
__device__ __forceinline__ void ldsm4(unsigned& r0, unsigned& r1,
                                      unsigned& r2, unsigned& r3, uint32_t a) {
    asm volatile("ldmatrix.sync.aligned.m8n8.x4.shared.b16 {%0,%1,%2,%3}, [%4];"
                 : "=r"(r0), "=r"(r1), "=r"(r2), "=r"(r3) : "r"(a));
}

// ---------------- fp32 -> fp16 convert (all 3 tensors, one launch) ----------
__global__ void to_half_all(const float4* __restrict__ a, __half2* __restrict__ da, int na,
                            const float4* __restrict__ b, __half2* __restrict__ db, int nb,
                            const float4* __restrict__ c, __half2* __restrict__ dc, int nc) {
    int i = blockIdx.x * blockDim.x + threadIdx.x;
    const float4* s; __half2* d; int idx;
    if (i < na)           { s = a; d = da; idx = i; }
    else if (i < na + nb) { s = b; d = db; idx = i - na; }
    else if (i < na + nb + nc) { s = c; d = dc; idx = i - na - nb; }
    else return;
    float4 v = s[idx];
    d[2 * idx]     = __floats2half2_rn(v.x, v.y);
    d[2 * idx + 1] = __floats2half2_rn(v.z, v.w);
}

// ---------------- gate: g[n] = sum_ds(Cr*Br - Ci*Bi), 4 lanes per n ---------
__global__ void compute_gate(const float4* __restrict__ Br, const float4* __restrict__ Bi,
                             const float4* __restrict__ Cr, const float4* __restrict__ Ci) {
    int t = blockIdx.x * blockDim.x + threadIdx.x;   // 0 .. 4*N1_-1
    int n = t >> 2, j = t & 3;
    if (n >= N1_) return;
    float4 cr = Cr[n * 4 + j], br = Br[n * 4 + j];
    float4 ci = Ci[n * 4 + j], bi = Bi[n * 4 + j];
    float s = 0.f;
    s = fmaf(cr.x, br.x, s); s = fmaf(-ci.x, bi.x, s);
    s = fmaf(cr.y, br.y, s); s = fmaf(-ci.y, bi.y, s);
    s = fmaf(cr.z, br.z, s); s = fmaf(-ci.z, bi.z, s);
    s = fmaf(cr.w, br.w, s); s = fmaf(-ci.w, bi.w, s);
    s += __shfl_down_sync(0xFFFFFFFFu, s, 2);
    s += __shfl_down_sync(0xFFFFFFFFu, s, 1);
    if (j == 0) g_gate[n] = s;
}

// ---------------- state emission helper -------------------------------------
__device__ __forceinline__ void emit_state(float* __restrict__ nr, float* __restrict__ ni,
                                           const float4* __restrict__ brp,
                                           const float4* __restrict__ bip,
                                           int row, int col, float v) {
    size_t off = ((size_t)row * N1_ + col) * 4;          // float4 units
    float4* pr = reinterpret_cast<float4*>(nr) + off;
    float4* pi = reinterpret_cast<float4*>(ni) + off;
    #pragma unroll
    for (int jj = 0; jj < 4; jj++) {
        float4 b = __ldg(&brp[(size_t)col * 4 + jj]);
        pr[jj] = make_float4(b.x * v, b.y * v, b.z * v, b.w * v);
    }
    #pragma unroll
    for (int jj = 0; jj < 4; jj++) {
        float4 b = __ldg(&bip[(size_t)col * 4 + jj]);
        pi[jj] = make_float4(b.x * v, b.y * v, b.z * v, b.w * v);
    }
}

// ---------------- TN GEMM: C[M,N] = A[M,K] * B[N,K]^T (fp16 mma + ldmatrix) -
// BM x 128 CTA tile, BK=32 halves, 4-stage cp.async pipeline, 256 threads.
template<int BM, bool FUSED>
__global__ __launch_bounds__(256, 2) void gemm_tn(
    const __half* __restrict__ A, const __half* __restrict__ B,
    float* __restrict__ Cf, __half* __restrict__ Ch, int ldc, int K,
    const float* __restrict__ Brs, const float* __restrict__ Bis,
    float* __restrict__ nr, float* __restrict__ ni, int write_state)
{
    constexpr int S   = 4;                    // pipeline stages
    constexpr int RS  = 40;                   // halves per smem row (32 + 8 pad)
    constexpr int WR  = (BM == 128) ? 4 : 2;  // warps along m
    constexpr int WNS = (BM == 128) ? 64 : 32;// warp n-extent
    constexpr int JN  = WNS / 8;
    constexpr int JP  = JN / 2;               // ldmatrix B pairs
    constexpr int AST = BM  * RS;             // halves per A stage
    constexpr int BST = 128 * RS;

    extern __shared__ __half sm[];
    __half* As = sm;
    __half* Bs = sm + S * AST;

    const int tid  = threadIdx.x;
    const int lane = tid & 31;
    const int wid  = tid >> 5;
    const int wm   = (wid % WR) * 32;
    const int wn   = (wid / WR) * WNS;
    const int gid  = lane >> 2;
    const int q    = lane & 3;
    const int row0 = blockIdx.y * BM;
    const int col0 = blockIdx.x * 128;

    const int lr = tid >> 2;                  // loader row
    const int ls = (tid & 3) * 8;             // loader half-offset (16B = 8 halves)

    // ldmatrix per-lane address offsets (bytes)
    const int lr8 = lane & 7;
    const int lg  = lane >> 3;                // 0..3
    const uint32_t sm_u = (uint32_t)__cvta_generic_to_shared(sm);
    const uint32_t A_u  = sm_u;
    const uint32_t B_u  = sm_u + S * AST * 2;
    const uint32_t a_off = (uint32_t)(((wm + (lg & 1) * 8 + lr8) * RS + (lg >> 1) * 8) * 2);
    const uint32_t b_off = (uint32_t)(((wn + (lg >> 1) * 8 + lr8) * RS + (lg & 1) * 8) * 2);

    float cr[2][JN][4];
    #pragma unroll
    for (int i = 0; i < 2; i++)
        #pragma unroll
        for (int j = 0; j < JN; j++)
            #pragma unroll
            for (int t = 0; t < 4; t++) cr[i][j][t] = 0.f;

    auto issue = [&](int st, int k0) {
        #pragma unroll
        for (int i = 0; i < BM / 64; i++) {
            int r = lr + i * 64;
            cpa16(&As[st * AST + r * RS + ls], A + (size_t)(row0 + r) * K + k0 + ls);
        }
        #pragma unroll
        for (int i = 0; i < 2; i++) {
            int r = lr + i * 64;
            cpa16(&Bs[st * BST + r * RS + ls], B + (size_t)(col0 + r) * K + k0 + ls);
        }
        asm volatile("cp.async.commit_group;\n");
    };

    auto compute = [&](int st) {
        const uint32_t ab = A_u + st * (AST * 2) + a_off;
        const uint32_t bb = B_u + st * (BST * 2) + b_off;
        #pragma unroll
        for (int ks = 0; ks < 2; ks++) {
            const uint32_t kbb = ks * 16 * 2;     // byte offset for this k-half
            unsigned a[2][4], bp[JP][4];
            #pragma unroll
            for (int i = 0; i < 2; i++)
                ldsm4(a[i][0], a[i][1], a[i][2], a[i][3],
                      ab + i * (16 * RS * 2) + kbb);
            #pragma unroll
            for (int jp = 0; jp < JP; jp++)
                ldsm4(bp[jp][0], bp[jp][1], bp[jp][2], bp[jp][3],
                      bb + jp * (16 * RS * 2) + kbb);
            #pragma unroll
            for (int i = 0; i < 2; i++)
                #pragma unroll
                for (int j = 0; j < JN; j++) {
                    const unsigned b0 = bp[j >> 1][(j & 1) * 2];
                    const unsigned b1 = bp[j >> 1][(j & 1) * 2 + 1];
                    asm volatile(
                        "mma.sync.aligned.m16n8k16.row.col.f32.f16.f16.f32 "
                        "{%0,%1,%2,%3}, {%4,%5,%6,%7}, {%8,%9}, {%0,%1,%2,%3};\n"
                        : "+f"(cr[i][j][0]), "+f"(cr[i][j][1]),
                          "+f"(cr[i][j][2]), "+f"(cr[i][j][3])
                        : "r"(a[i][0]), "r"(a[i][1]), "r"(a[i][2]), "r"(a[i][3]),
                          "r"(b0), "r"(b1));
                }
        }
    };

    const int nt = K / 32;
    #pragma unroll
    for (int s = 0; s < S - 1; s++) issue(s, s * 32);
    asm volatile("cp.async.wait_group 2;\n");
    __syncthreads();

    for (int kt = 0; kt < nt; kt++) {
        int nk = kt + S - 1;
        if (nk < nt) issue(nk % S, nk * 32);
        else asm volatile("cp.async.commit_group;\n");
        compute(kt % S);
        asm volatile("cp.async.wait_group 2;\n");
        __syncthreads();
    }

    // ---------------- epilogue ----------------
    if (!FUSED) {
        #pragma unroll
        for (int i = 0; i < 2; i++)
            #pragma unroll
            for (int j = 0; j < JN; j++) {
                int r  = row0 + wm + i * 16 + gid;
                int cn = col0 + wn + j * 8 + q * 2;
                *reinterpret_cast<float2*>(Cf + (size_t)r * ldc + cn) =
                    make_float2(cr[i][j][0], cr[i][j][1]);
                *reinterpret_cast<float2*>(Cf + (size_t)(r + 8) * ldc + cn) =
                    make_float2(cr[i][j][2], cr[i][j][3]);
            }
    } else {
        const float4* brp = reinterpret_cast<const float4*>(Brs);
        const float4* bip = reinterpret_cast<const float4*>(Bis);
        #pragma unroll
        for (int i = 0; i < 2; i++)
            #pragma unroll
            for (int j = 0; j < JN; j++) {
                int r  = row0 + wm + i * 16 + gid;
                int cn = col0 + wn + j * 8 + q * 2;
                float g0 = g_gate[cn], g1 = g_gate[cn + 1];
                *reinterpret_cast<__half2*>(Ch + (size_t)r * ldc + cn) =
                    __floats2half2_rn(cr[i][j][0] * g0, cr[i][j][1] * g1);
                *reinterpret_cast<__half2*>(Ch + (size_t)(r + 8) * ldc + cn) =
                    __floats2half2_rn(cr[i][j][2] * g0, cr[i][j][3] * g1);
                if (write_state) {
                    emit_state(nr, ni, brp, bip, r,     cn,     cr[i][j][0]);
                    emit_state(nr, ni, brp, bip, r,     cn + 1, cr[i][j][1]);
                    emit_state(nr, ni, brp, bip, r + 8, cn,     cr[i][j][2]);
                    emit_state(nr, ni, brp, bip, r + 8, cn + 1, cr[i][j][3]);
                }
            }
    }
}

// ---------------- rmsnorm + residual ----------------------------------------
__global__ __launch_bounds__(256) void rms_kernel(const float* __restrict__ x,
                                                  const float* __restrict__ w,
                                                  float* __restrict__ out)
{
    const int row = blockIdx.x;
    const float* o = g_o + (size_t)row * D_;
    float s = 0.f;
    for (int d = threadIdx.x; d < D_; d += 256) {
        float v = o[d];
        s = fmaf(v, v, s);
    }
    __shared__ float red[8];
    #pragma unroll
    for (int off = 16; off; off >>= 1) s += __shfl_xor_sync(0xFFFFFFFFu, s, off);
    if ((threadIdx.x & 31) == 0) red[threadIdx.x >> 5] = s;
    __syncthreads();
    if (threadIdx.x < 8) {
        float t = red[threadIdx.x];
        #pragma unroll
        for (int off = 4; off; off >>= 1) t += __shfl_xor_sync(0xFFu, t, off);
        if (threadIdx.x == 0) red[0] = t;
    }
    __syncthreads();
    const float scale = rsqrtf(red[0] * (1.0f / D_) + 1.1920928955078125e-7f);
    for (int d = threadIdx.x; d < D_; d += 256) {
        out[(size_t)row * D_ + d] =
            x[(size_t)row * D_ + d] + o[d] * scale * w[d];
    }
}

// ---------------- launch -----------------------------------------------------
extern "C" void kernel_launch(void* const* d_in, const int* in_sizes, int n_in,
                              void* d_out, int out_size)
{
    const float* x     = (const float*)d_in[0];
    const float* W_in  = (const float*)d_in[1];
    const float* W_out = (const float*)d_in[2];
    // d_in[3] = A_theta: dead (initial state is zero)
    const float* Br    = (const float*)d_in[4];
    const float* Bi    = (const float*)d_in[5];
    const float* Cr    = (const float*)d_in[6];
    const float* Ci    = (const float*)d_in[7];
    const float* nw    = (const float*)d_in[8];

    float* out0 = (float*)d_out;
    const long long FULL =
        (long long)BL_ * D_ + 2LL * BL_ * N1_ * DS_;   // 136,314,880
    const int write_state = ((long long)out_size >= FULL) ? 1 : 0;
    float* nr = out0 + (size_t)BL_ * D_;
    float* ni = nr + (size_t)BL_ * N1_ * DS_;

    void *w1_p = nullptr, *w2_p = nullptr, *xh_p = nullptr, *yh_p = nullptr, *o_p = nullptr;
    cudaGetSymbolAddress(&w1_p, g_Wh1);
    cudaGetSymbolAddress(&w2_p, g_Wh2);
    cudaGetSymbolAddress(&xh_p, g_xh);
    cudaGetSymbolAddress(&yh_p, g_yh);
    cudaGetSymbolAddress(&o_p,  g_o);

    const int SM1 = 4 * (128 + 128) * 40 * 2;   // 81,920 B
    const int SM2 = 4 * ( 64 + 128) * 40 * 2;   // 61,440 B
    cudaFuncSetAttribute(gemm_tn<128, true >, cudaFuncAttributeMaxDynamicSharedMemorySize, SM1);
    cudaFuncSetAttribute(gemm_tn< 64, false>, cudaFuncAttributeMaxDynamicSharedMemorySize, SM2);

    // convert inputs to fp16 (single launch)
    const int na = N1_ * D_ / 4, nb = D_ * N1_ / 4, nc = BL_ * D_ / 4;
    to_half_all<<<(na + nb + nc + 255) / 256, 256>>>(
        (const float4*)W_in,  (__half2*)w1_p, na,
        (const float4*)W_out, (__half2*)w2_p, nb,
        (const float4*)x,     (__half2*)xh_p, nc);

    compute_gate<<<(4 * N1_) / 256, 256>>>((const float4*)Br, (const float4*)Bi,
                                           (const float4*)Cr, (const float4*)Ci);

    // GEMM1 (fused): xi = x @ W_in^T -> y(half) / nr / ni.  M=1024,N=4096,K=2048
    gemm_tn<128, true><<<dim3(N1_ / 128, BL_ / 128), 256, SM1>>>(
        (const __half*)xh_p, (const __half*)w1_p, nullptr, (__half*)yh_p, N1_, D_,
        Br, Bi, nr, ni, write_state);

    // GEMM2: out = y @ W_out^T.  M=1024,N=2048,K=4096  (64-row tiles -> 256 CTAs)
    gemm_tn<64, false><<<dim3(D_ / 128, BL_ / 64), 256, SM2>>>(
        (const __half*)yh_p, (const __half*)w2_p, (float*)o_p, nullptr, D_, N1_,
        nullptr, nullptr, nullptr, nullptr, 0);

    // out0 = x + rmsnorm(out) * norm_w
    rms_kernel<<<BL_, 256>>>(x, nw, out0);
}